// round 7
// baseline (speedup 1.0000x reference)
#include <cuda_runtime.h>
#include <cuda_fp16.h>
#include <cstdint>

// ============================================================================
// out[8192,2048] = x[8192,2048] @ W[2048,2048]^T + bias
// fp16 single-term GEMM on HMMA (mma.sync m16n8k16.f32.f16.f16.f32).
// R7: R6 + register frag double-buffering ONLY (inline offsets, compressed
//     loader keep register count ~242 < 255 cap at launch_bounds(128,2)).
// CTA 128x128x64, 128 thr, warp grid 2x2, warp tile 64x64, 3-stage cp.async,
// 96KB smem/CTA -> 2 CTAs/SM.
// ============================================================================

#define M_TOTAL 8192
#define N_TOTAL 2048
#define K_TOTAL 2048

#define MT 128
#define NT 128
#define KT 64
#define KITERS (K_TOTAL / KT)   // 32
#define NSTAGE 3

#define M_TILES (M_TOTAL / MT)  // 64
#define N_TILES (N_TOTAL / NT)  // 16

#define OFF_A 0
#define OFF_B 16384
#define STAGE_BYTES 32768
#define SMEM_REQ (NSTAGE * STAGE_BYTES)   // 98304

__device__ __half g_xh[M_TOTAL * K_TOTAL];
__device__ __half g_wh[N_TOTAL * K_TOTAL];

// ---------------------------------------------------------------------------
__device__ __forceinline__ uint32_t smem_u32(const void* p) {
    uint32_t a;
    asm("{ .reg .u64 t; cvta.to.shared.u64 t, %1; cvt.u32.u64 %0, t; }"
        : "=r"(a) : "l"(p));
    return a;
}

__device__ __forceinline__ void cp_async16(uint32_t dst, const void* src) {
    asm volatile("cp.async.cg.shared.global [%0], [%1], 16;"
                 :: "r"(dst), "l"(src));
}
#define CP_COMMIT() asm volatile("cp.async.commit_group;" ::: "memory")
#define CP_WAIT1()  asm volatile("cp.async.wait_group 1;" ::: "memory")

__device__ __forceinline__ void ldsm_x4(uint32_t* r, uint32_t addr) {
    asm volatile("ldmatrix.sync.aligned.m8n8.x4.shared.b16 {%0,%1,%2,%3}, [%4];"
                 : "=r"(r[0]), "=r"(r[1]), "=r"(r[2]), "=r"(r[3])
                 : "r"(addr));
}

__device__ __forceinline__ void mma16816(float* c, const uint32_t* a, const uint32_t* b) {
    asm volatile(
        "mma.sync.aligned.m16n8k16.row.col.f32.f16.f16.f32 "
        "{%0,%1,%2,%3}, {%4,%5,%6,%7}, {%8,%9}, {%0,%1,%2,%3};"
        : "+f"(c[0]), "+f"(c[1]), "+f"(c[2]), "+f"(c[3])
        : "r"(a[0]), "r"(a[1]), "r"(a[2]), "r"(a[3]),
          "r"(b[0]), "r"(b[1]));
}

// ---------------------------------------------------------------------------
// Kernel 1: convert fp32 -> fp16, 64B in / 32B out per thread
// ---------------------------------------------------------------------------
__global__ void __launch_bounds__(256) convert_fp16_kernel(
    const float4* __restrict__ src,
    float4* __restrict__ dst,
    int n16)
{
    int i = blockIdx.x * blockDim.x + threadIdx.x;
    if (i >= n16) return;
    float4 v0 = src[4 * i];
    float4 v1 = src[4 * i + 1];
    float4 v2 = src[4 * i + 2];
    float4 v3 = src[4 * i + 3];

    __half2 h0 = __halves2half2(__float2half_rn(v0.x), __float2half_rn(v0.y));
    __half2 h1 = __halves2half2(__float2half_rn(v0.z), __float2half_rn(v0.w));
    __half2 h2 = __halves2half2(__float2half_rn(v1.x), __float2half_rn(v1.y));
    __half2 h3 = __halves2half2(__float2half_rn(v1.z), __float2half_rn(v1.w));
    __half2 h4 = __halves2half2(__float2half_rn(v2.x), __float2half_rn(v2.y));
    __half2 h5 = __halves2half2(__float2half_rn(v2.z), __float2half_rn(v2.w));
    __half2 h6 = __halves2half2(__float2half_rn(v3.x), __float2half_rn(v3.y));
    __half2 h7 = __halves2half2(__float2half_rn(v3.z), __float2half_rn(v3.w));

    float4 o0, o1;
    o0.x = __uint_as_float(*(uint32_t*)&h0);
    o0.y = __uint_as_float(*(uint32_t*)&h1);
    o0.z = __uint_as_float(*(uint32_t*)&h2);
    o0.w = __uint_as_float(*(uint32_t*)&h3);
    o1.x = __uint_as_float(*(uint32_t*)&h4);
    o1.y = __uint_as_float(*(uint32_t*)&h5);
    o1.z = __uint_as_float(*(uint32_t*)&h6);
    o1.w = __uint_as_float(*(uint32_t*)&h7);
    dst[2 * i]     = o0;
    dst[2 * i + 1] = o1;
}

// ---------------------------------------------------------------------------
// Kernel 2: fp16 GEMM via HMMA, 3-stage cp.async + frag double buffer
// ---------------------------------------------------------------------------
__global__ void __launch_bounds__(128, 2) fp16_gemm_kernel(
    float* __restrict__ out,
    const float* __restrict__ bias,
    const __half* __restrict__ xh,
    const __half* __restrict__ wh)
{
    extern __shared__ __align__(1024) char smem[];
    const uint32_t sb = smem_u32(smem);

    const int tid = threadIdx.x;
    const int lane = tid & 31;
    const int wid = tid >> 5;
    const int warp_m = wid >> 1;   // 0..1
    const int warp_n = wid & 1;    // 0..1

    const int n_tile = blockIdx.x & (N_TILES - 1);
    const int m_tile = blockIdx.x >> 4;
    const int m0 = m_tile * MT;
    const int n0 = n_tile * NT;

    // ---- register-compressed loader layout ----
    const int lrow = tid >> 3;
    const int lchk = tid & 7;
    const uint32_t dsw0 = (uint32_t)(lrow * 128 + ((lchk ^ (lrow & 7)) << 4));
    const __half* gA0 = xh + (size_t)(m0 + lrow) * K_TOTAL + lchk * 8;
    const __half* gB0 = wh + (size_t)(n0 + lrow) * K_TOTAL + lchk * 8;

    auto load_stage = [&](int stage, int k0) {
        uint32_t sbase = sb + stage * STAGE_BYTES + dsw0;
        const __half* pA = gA0 + k0;
        const __half* pB = gB0 + k0;
#pragma unroll
        for (int i = 0; i < 8; i++) {
            cp_async16(sbase + OFF_A + i * 2048, pA + (size_t)i * (16 * K_TOTAL));
            cp_async16(sbase + OFF_B + i * 2048, pB + (size_t)i * (16 * K_TOTAL));
        }
    };

    // ---- ldmatrix per-lane base terms ----
    const int a_row_l = warp_m * 64 + (lane & 15);
    const int a_kadd  = lane >> 4;
    const int b_row_l = warp_n * 64 + (lane & 7) + ((lane >> 4) << 3);
    const int b_kadd  = (lane >> 3) & 1;

    float acc[4][8][4];
#pragma unroll
    for (int mt = 0; mt < 4; mt++)
#pragma unroll
        for (int nt = 0; nt < 8; nt++)
#pragma unroll
            for (int j = 0; j < 4; j++) acc[mt][nt][j] = 0.0f;

    // ---- prologue ----
    load_stage(0, 0);
    CP_COMMIT();
    load_stage(1, KT);
    CP_COMMIT();

    // frag double buffers (+32 regs over single)
    uint32_t a[2][4][4], b[2][8][2];

    auto ld_frags = [&](int buf, int kc, uint32_t sA, uint32_t sB) {
#pragma unroll
        for (int mt = 0; mt < 4; mt++) {
            int row = a_row_l + mt * 16;
            int ch = kc * 2 + a_kadd;
            uint32_t off = (uint32_t)(row * 128 + ((ch ^ (row & 7)) << 4));
            ldsm_x4(a[buf][mt], sA + off);
        }
#pragma unroll
        for (int np = 0; np < 4; np++) {
            int row = b_row_l + np * 16;
            int ch = kc * 2 + b_kadd;
            uint32_t off = (uint32_t)(row * 128 + ((ch ^ (row & 7)) << 4));
            uint32_t t[4];
            ldsm_x4(t, sB + off);
            b[buf][np * 2][0] = t[0]; b[buf][np * 2][1] = t[1];
            b[buf][np * 2 + 1][0] = t[2]; b[buf][np * 2 + 1][1] = t[3];
        }
    };

    // ---- mainloop ----
    for (int ks = 0; ks < KITERS; ks++) {
        CP_WAIT1();
        __syncthreads();

        if (ks + 2 < KITERS) load_stage((ks + 2) % NSTAGE, (ks + 2) * KT);
        CP_COMMIT();

        const uint32_t sbase = sb + (ks % NSTAGE) * STAGE_BYTES;
        const uint32_t sA = sbase + OFF_A;
        const uint32_t sB = sbase + OFF_B;

        ld_frags(0, 0, sA, sB);

#pragma unroll
        for (int kc = 0; kc < 4; kc++) {
            int cur = kc & 1;
            if (kc < 3) ld_frags(cur ^ 1, kc + 1, sA, sB);
#pragma unroll
            for (int mt = 0; mt < 4; mt++) {
#pragma unroll
                for (int nt = 0; nt < 8; nt++) {
                    mma16816(acc[mt][nt], a[cur][mt], b[cur][nt]);
                }
            }
        }
    }

    // ---- epilogue: bias + store ----
    const int r0 = lane >> 2;
    const int c0 = (lane & 3) * 2;
#pragma unroll
    for (int mt = 0; mt < 4; mt++) {
        int row = m0 + warp_m * 64 + mt * 16 + r0;
#pragma unroll
        for (int nt = 0; nt < 8; nt++) {
            int col = n0 + warp_n * 64 + nt * 8 + c0;
            float bx = __ldg(bias + col);
            float by = __ldg(bias + col + 1);
            float2 v0 = make_float2(acc[mt][nt][0] + bx, acc[mt][nt][1] + by);
            float2 v1 = make_float2(acc[mt][nt][2] + bx, acc[mt][nt][3] + by);
            *(float2*)(out + (size_t)row * N_TOTAL + col) = v0;
            *(float2*)(out + (size_t)(row + 8) * N_TOTAL + col) = v1;
        }
    }
}

// ---------------------------------------------------------------------------
// Host side
// ---------------------------------------------------------------------------
extern "C" void kernel_launch(void* const* d_in, const int* in_sizes, int n_in,
                              void* d_out, int out_size) {
    const float* x    = (const float*)d_in[0];
    const float* w    = (const float*)d_in[1];
    const float* bias = (const float*)d_in[2];
    float* out = (float*)d_out;

    __half *xh, *wh;
    cudaGetSymbolAddress((void**)&xh, g_xh);
    cudaGetSymbolAddress((void**)&wh, g_wh);

    {
        int n16x = (M_TOTAL * K_TOTAL) / 16;
        int n16w = (N_TOTAL * K_TOTAL) / 16;
        convert_fp16_kernel<<<(n16x + 255) / 256, 256>>>(
            (const float4*)x, (float4*)xh, n16x);
        convert_fp16_kernel<<<(n16w + 255) / 256, 256>>>(
            (const float4*)w, (float4*)wh, n16w);
    }

    static bool attr_set = false;
    if (!attr_set) {
        cudaFuncSetAttribute(fp16_gemm_kernel,
                             cudaFuncAttributeMaxDynamicSharedMemorySize, SMEM_REQ);
        attr_set = true;
    }
    fp16_gemm_kernel<<<M_TILES * N_TILES, 128, SMEM_REQ>>>(out, bias, xh, wh);
}

// round 8
// speedup vs baseline: 1.0024x; 1.0024x over previous
#include <cuda_runtime.h>
#include <cuda_fp16.h>
#include <cstdint>

// ============================================================================
// out[8192,2048] = x[8192,2048] @ W[2048,2048]^T + bias
// fp16 single-term GEMM on HMMA (mma.sync m16n8k16.f32.f16.f16.f32).
// R8: occupancy experiment — 3 warps/SMSP issuing HMMA.
//   CTA tile 64x128x64, 128 thr, 4 warps (warp tile 64x32), 3-stage cp.async,
//   24KB/stage -> 72KB smem/CTA -> 3 CTAs/SM (12 warps/SM, 3/SMSP).
//   Converts merged into one kernel.
// ============================================================================

#define M_TOTAL 8192
#define N_TOTAL 2048
#define K_TOTAL 2048

#define MT 64
#define NT 128
#define KT 64
#define KITERS (K_TOTAL / KT)   // 32
#define NSTAGE 3

#define M_TILES (M_TOTAL / MT)  // 128
#define N_TILES (N_TOTAL / NT)  // 16

#define OFF_A 0
#define OFF_B 8192
#define STAGE_BYTES 24576
#define SMEM_REQ (NSTAGE * STAGE_BYTES)   // 73728

__device__ __half g_xh[M_TOTAL * K_TOTAL];
__device__ __half g_wh[N_TOTAL * K_TOTAL];

// ---------------------------------------------------------------------------
__device__ __forceinline__ uint32_t smem_u32(const void* p) {
    uint32_t a;
    asm("{ .reg .u64 t; cvta.to.shared.u64 t, %1; cvt.u32.u64 %0, t; }"
        : "=r"(a) : "l"(p));
    return a;
}

__device__ __forceinline__ void cp_async16(uint32_t dst, const void* src) {
    asm volatile("cp.async.cg.shared.global [%0], [%1], 16;"
                 :: "r"(dst), "l"(src));
}
#define CP_COMMIT() asm volatile("cp.async.commit_group;" ::: "memory")
#define CP_WAIT1()  asm volatile("cp.async.wait_group 1;" ::: "memory")

__device__ __forceinline__ void ldsm_x4(uint32_t* r, uint32_t addr) {
    asm volatile("ldmatrix.sync.aligned.m8n8.x4.shared.b16 {%0,%1,%2,%3}, [%4];"
                 : "=r"(r[0]), "=r"(r[1]), "=r"(r[2]), "=r"(r[3])
                 : "r"(addr));
}

__device__ __forceinline__ void mma16816(float* c, const uint32_t* a, const uint32_t* b) {
    asm volatile(
        "mma.sync.aligned.m16n8k16.row.col.f32.f16.f16.f32 "
        "{%0,%1,%2,%3}, {%4,%5,%6,%7}, {%8,%9}, {%0,%1,%2,%3};"
        : "+f"(c[0]), "+f"(c[1]), "+f"(c[2]), "+f"(c[3])
        : "r"(a[0]), "r"(a[1]), "r"(a[2]), "r"(a[3]),
          "r"(b[0]), "r"(b[1]));
}

// ---------------------------------------------------------------------------
// Kernel 1: convert fp32 -> fp16 for BOTH x and W in one launch.
// ---------------------------------------------------------------------------
__global__ void __launch_bounds__(256) convert_both_kernel(
    const float4* __restrict__ srcx, float4* __restrict__ dstx, int n16x,
    const float4* __restrict__ srcw, float4* __restrict__ dstw, int n16w)
{
    int i = blockIdx.x * blockDim.x + threadIdx.x;
    const float4* src;
    float4* dst;
    if (i < n16x) {
        src = srcx + 4 * (size_t)i;
        dst = dstx + 2 * (size_t)i;
    } else {
        int j = i - n16x;
        if (j >= n16w) return;
        src = srcw + 4 * (size_t)j;
        dst = dstw + 2 * (size_t)j;
    }
    float4 v0 = src[0];
    float4 v1 = src[1];
    float4 v2 = src[2];
    float4 v3 = src[3];

    __half2 h0 = __halves2half2(__float2half_rn(v0.x), __float2half_rn(v0.y));
    __half2 h1 = __halves2half2(__float2half_rn(v0.z), __float2half_rn(v0.w));
    __half2 h2 = __halves2half2(__float2half_rn(v1.x), __float2half_rn(v1.y));
    __half2 h3 = __halves2half2(__float2half_rn(v1.z), __float2half_rn(v1.w));
    __half2 h4 = __halves2half2(__float2half_rn(v2.x), __float2half_rn(v2.y));
    __half2 h5 = __halves2half2(__float2half_rn(v2.z), __float2half_rn(v2.w));
    __half2 h6 = __halves2half2(__float2half_rn(v3.x), __float2half_rn(v3.y));
    __half2 h7 = __halves2half2(__float2half_rn(v3.z), __float2half_rn(v3.w));

    float4 o0, o1;
    o0.x = __uint_as_float(*(uint32_t*)&h0);
    o0.y = __uint_as_float(*(uint32_t*)&h1);
    o0.z = __uint_as_float(*(uint32_t*)&h2);
    o0.w = __uint_as_float(*(uint32_t*)&h3);
    o1.x = __uint_as_float(*(uint32_t*)&h4);
    o1.y = __uint_as_float(*(uint32_t*)&h5);
    o1.z = __uint_as_float(*(uint32_t*)&h6);
    o1.w = __uint_as_float(*(uint32_t*)&h7);
    dst[0] = o0;
    dst[1] = o1;
}

// ---------------------------------------------------------------------------
// Kernel 2: fp16 GEMM via HMMA — 64x128 CTA tile, warp tile 64x32,
//           3-stage cp.async, 3 CTAs/SM.
// ---------------------------------------------------------------------------
__global__ void __launch_bounds__(128, 3) fp16_gemm_kernel(
    float* __restrict__ out,
    const float* __restrict__ bias,
    const __half* __restrict__ xh,
    const __half* __restrict__ wh)
{
    extern __shared__ __align__(1024) char smem[];
    const uint32_t sb = smem_u32(smem);

    const int tid = threadIdx.x;
    const int lane = tid & 31;
    const int wid = tid >> 5;          // warp_n = wid (0..3), each 32 N cols

    const int n_tile = blockIdx.x & (N_TILES - 1);
    const int m_tile = blockIdx.x >> 4;
    const int m0 = m_tile * MT;
    const int n0 = n_tile * NT;

    // ---- register-compressed loader ----
    // A subtile: 64 rows x 128B (8KB). rows = (tid>>3) + i*16, i=0..3
    // B subtile: 128 rows x 128B (16KB). rows = (tid>>3) + i*16, i=0..7
    const int lrow = tid >> 3;
    const int lchk = tid & 7;
    const uint32_t dsw0 = (uint32_t)(lrow * 128 + ((lchk ^ (lrow & 7)) << 4));
    const __half* gA0 = xh + (size_t)(m0 + lrow) * K_TOTAL + lchk * 8;
    const __half* gB0 = wh + (size_t)(n0 + lrow) * K_TOTAL + lchk * 8;

    auto load_stage = [&](int stage, int k0) {
        uint32_t sbase = sb + stage * STAGE_BYTES + dsw0;
        const __half* pA = gA0 + k0;
        const __half* pB = gB0 + k0;
#pragma unroll
        for (int i = 0; i < 4; i++)
            cp_async16(sbase + OFF_A + i * 2048, pA + (size_t)i * (16 * K_TOTAL));
#pragma unroll
        for (int i = 0; i < 8; i++)
            cp_async16(sbase + OFF_B + i * 2048, pB + (size_t)i * (16 * K_TOTAL));
    };

    // ---- ldmatrix per-lane base terms ----
    const int a_row_l = lane & 15;            // + mt*16, all warps share A
    const int a_kadd  = lane >> 4;
    const int b_row_l = wid * 32 + (lane & 7) + ((lane >> 4) << 3);  // + np*16
    const int b_kadd  = (lane >> 3) & 1;

    float acc[4][4][4];
#pragma unroll
    for (int mt = 0; mt < 4; mt++)
#pragma unroll
        for (int nt = 0; nt < 4; nt++)
#pragma unroll
            for (int j = 0; j < 4; j++) acc[mt][nt][j] = 0.0f;

    // ---- prologue ----
    load_stage(0, 0);
    CP_COMMIT();
    load_stage(1, KT);
    CP_COMMIT();

    // ---- mainloop ----
    for (int ks = 0; ks < KITERS; ks++) {
        CP_WAIT1();
        __syncthreads();

        if (ks + 2 < KITERS) load_stage((ks + 2) % NSTAGE, (ks + 2) * KT);
        CP_COMMIT();

        const uint32_t sbase = sb + (ks % NSTAGE) * STAGE_BYTES;
        const uint32_t sA = sbase + OFF_A;
        const uint32_t sB = sbase + OFF_B;

#pragma unroll
        for (int kc = 0; kc < 4; kc++) {
            uint32_t a[4][4], b[4][2];

#pragma unroll
            for (int mt = 0; mt < 4; mt++) {
                int row = a_row_l + mt * 16;
                int ch = kc * 2 + a_kadd;
                uint32_t off = (uint32_t)(row * 128 + ((ch ^ (row & 7)) << 4));
                ldsm_x4(a[mt], sA + off);
            }
#pragma unroll
            for (int np = 0; np < 2; np++) {
                int row = b_row_l + np * 16;
                int ch = kc * 2 + b_kadd;
                uint32_t off = (uint32_t)(row * 128 + ((ch ^ (row & 7)) << 4));
                uint32_t t[4];
                ldsm_x4(t, sB + off);
                b[np * 2][0] = t[0]; b[np * 2][1] = t[1];
                b[np * 2 + 1][0] = t[2]; b[np * 2 + 1][1] = t[3];
            }

#pragma unroll
            for (int mt = 0; mt < 4; mt++) {
#pragma unroll
                for (int nt = 0; nt < 4; nt++) {
                    mma16816(acc[mt][nt], a[mt], b[nt]);
                }
            }
        }
    }

    // ---- epilogue: bias + store ----
    const int r0 = lane >> 2;
    const int c0 = (lane & 3) * 2;
#pragma unroll
    for (int mt = 0; mt < 4; mt++) {
        int row = m0 + mt * 16 + r0;
#pragma unroll
        for (int nt = 0; nt < 4; nt++) {
            int col = n0 + wid * 32 + nt * 8 + c0;
            float bx = __ldg(bias + col);
            float by = __ldg(bias + col + 1);
            float2 v0 = make_float2(acc[mt][nt][0] + bx, acc[mt][nt][1] + by);
            float2 v1 = make_float2(acc[mt][nt][2] + bx, acc[mt][nt][3] + by);
            *(float2*)(out + (size_t)row * N_TOTAL + col) = v0;
            *(float2*)(out + (size_t)(row + 8) * N_TOTAL + col) = v1;
        }
    }
}

// ---------------------------------------------------------------------------
// Host side
// ---------------------------------------------------------------------------
extern "C" void kernel_launch(void* const* d_in, const int* in_sizes, int n_in,
                              void* d_out, int out_size) {
    const float* x    = (const float*)d_in[0];
    const float* w    = (const float*)d_in[1];
    const float* bias = (const float*)d_in[2];
    float* out = (float*)d_out;

    __half *xh, *wh;
    cudaGetSymbolAddress((void**)&xh, g_xh);
    cudaGetSymbolAddress((void**)&wh, g_wh);

    {
        int n16x = (M_TOTAL * K_TOTAL) / 16;   // 1,048,576
        int n16w = (N_TOTAL * K_TOTAL) / 16;   //   262,144
        int total = n16x + n16w;
        convert_both_kernel<<<(total + 255) / 256, 256>>>(
            (const float4*)x, (float4*)xh, n16x,
            (const float4*)w, (float4*)wh, n16w);
    }

    static bool attr_set = false;
    if (!attr_set) {
        cudaFuncSetAttribute(fp16_gemm_kernel,
                             cudaFuncAttributeMaxDynamicSharedMemorySize, SMEM_REQ);
        attr_set = true;
    }
    fp16_gemm_kernel<<<M_TILES * N_TILES, 128, SMEM_REQ>>>(out, bias, xh, wh);
}

// round 9
// speedup vs baseline: 1.0753x; 1.0727x over previous
#include <cuda_runtime.h>
#include <cuda_fp16.h>
#include <cstdint>

// ============================================================================
// out[8192,2048] = x[8192,2048] @ W[2048,2048]^T + bias
// fp16 single-term GEMM on HMMA (mma.sync m16n8k16.f32.f16.f16.f32).
// R9: R6 GEMM config (best measured: 128x128x64, 2 CTAs/SM) with
//     stage-head reorder (kc0 LDSM issued before cp.async burst), plus the
//     merged one-launch convert kernel from R8.
// ============================================================================

#define M_TOTAL 8192
#define N_TOTAL 2048
#define K_TOTAL 2048

#define MT 128
#define NT 128
#define KT 64
#define KITERS (K_TOTAL / KT)   // 32
#define NSTAGE 3

#define M_TILES (M_TOTAL / MT)  // 64
#define N_TILES (N_TOTAL / NT)  // 16

#define OFF_A 0
#define OFF_B 16384
#define STAGE_BYTES 32768
#define SMEM_REQ (NSTAGE * STAGE_BYTES)   // 98304

__device__ __half g_xh[M_TOTAL * K_TOTAL];
__device__ __half g_wh[N_TOTAL * K_TOTAL];

// ---------------------------------------------------------------------------
__device__ __forceinline__ uint32_t smem_u32(const void* p) {
    uint32_t a;
    asm("{ .reg .u64 t; cvta.to.shared.u64 t, %1; cvt.u32.u64 %0, t; }"
        : "=r"(a) : "l"(p));
    return a;
}

__device__ __forceinline__ void cp_async16(uint32_t dst, const void* src) {
    asm volatile("cp.async.cg.shared.global [%0], [%1], 16;"
                 :: "r"(dst), "l"(src));
}
#define CP_COMMIT() asm volatile("cp.async.commit_group;" ::: "memory")
#define CP_WAIT1()  asm volatile("cp.async.wait_group 1;" ::: "memory")

__device__ __forceinline__ void ldsm_x4(uint32_t* r, uint32_t addr) {
    asm volatile("ldmatrix.sync.aligned.m8n8.x4.shared.b16 {%0,%1,%2,%3}, [%4];"
                 : "=r"(r[0]), "=r"(r[1]), "=r"(r[2]), "=r"(r[3])
                 : "r"(addr));
}

__device__ __forceinline__ void mma16816(float* c, const uint32_t* a, const uint32_t* b) {
    asm volatile(
        "mma.sync.aligned.m16n8k16.row.col.f32.f16.f16.f32 "
        "{%0,%1,%2,%3}, {%4,%5,%6,%7}, {%8,%9}, {%0,%1,%2,%3};"
        : "+f"(c[0]), "+f"(c[1]), "+f"(c[2]), "+f"(c[3])
        : "r"(a[0]), "r"(a[1]), "r"(a[2]), "r"(a[3]),
          "r"(b[0]), "r"(b[1]));
}

// ---------------------------------------------------------------------------
// Kernel 1: convert fp32 -> fp16 for BOTH x and W in one launch.
// ---------------------------------------------------------------------------
__global__ void __launch_bounds__(256) convert_both_kernel(
    const float4* __restrict__ srcx, float4* __restrict__ dstx, int n16x,
    const float4* __restrict__ srcw, float4* __restrict__ dstw, int n16w)
{
    int i = blockIdx.x * blockDim.x + threadIdx.x;
    const float4* src;
    float4* dst;
    if (i < n16x) {
        src = srcx + 4 * (size_t)i;
        dst = dstx + 2 * (size_t)i;
    } else {
        int j = i - n16x;
        if (j >= n16w) return;
        src = srcw + 4 * (size_t)j;
        dst = dstw + 2 * (size_t)j;
    }
    float4 v0 = src[0];
    float4 v1 = src[1];
    float4 v2 = src[2];
    float4 v3 = src[3];

    __half2 h0 = __halves2half2(__float2half_rn(v0.x), __float2half_rn(v0.y));
    __half2 h1 = __halves2half2(__float2half_rn(v0.z), __float2half_rn(v0.w));
    __half2 h2 = __halves2half2(__float2half_rn(v1.x), __float2half_rn(v1.y));
    __half2 h3 = __halves2half2(__float2half_rn(v1.z), __float2half_rn(v1.w));
    __half2 h4 = __halves2half2(__float2half_rn(v2.x), __float2half_rn(v2.y));
    __half2 h5 = __halves2half2(__float2half_rn(v2.z), __float2half_rn(v2.w));
    __half2 h6 = __halves2half2(__float2half_rn(v3.x), __float2half_rn(v3.y));
    __half2 h7 = __halves2half2(__float2half_rn(v3.z), __float2half_rn(v3.w));

    float4 o0, o1;
    o0.x = __uint_as_float(*(uint32_t*)&h0);
    o0.y = __uint_as_float(*(uint32_t*)&h1);
    o0.z = __uint_as_float(*(uint32_t*)&h2);
    o0.w = __uint_as_float(*(uint32_t*)&h3);
    o1.x = __uint_as_float(*(uint32_t*)&h4);
    o1.y = __uint_as_float(*(uint32_t*)&h5);
    o1.z = __uint_as_float(*(uint32_t*)&h6);
    o1.w = __uint_as_float(*(uint32_t*)&h7);
    dst[0] = o0;
    dst[1] = o1;
}

// ---------------------------------------------------------------------------
// Kernel 2: fp16 GEMM via HMMA — 128x128 tile, 256 thr, warp grid 2x2,
//           warp tile 64x64, 3-stage cp.async, 2 CTAs/SM.
//           Stage head reordered: kc0 LDSM before the cp.async burst.
// ---------------------------------------------------------------------------
__global__ void __launch_bounds__(128, 2) fp16_gemm_kernel(
    float* __restrict__ out,
    const float* __restrict__ bias,
    const __half* __restrict__ xh,
    const __half* __restrict__ wh)
{
    extern __shared__ __align__(1024) char smem[];
    const uint32_t sb = smem_u32(smem);

    const int tid = threadIdx.x;
    const int lane = tid & 31;
    const int wid = tid >> 5;
    const int warp_m = wid >> 1;   // 0..1
    const int warp_n = wid & 1;    // 0..1

    const int n_tile = blockIdx.x & (N_TILES - 1);
    const int m_tile = blockIdx.x >> 4;
    const int m0 = m_tile * MT;
    const int n0 = n_tile * NT;

    // ---- register-compressed loader layout ----
    const int lrow = tid >> 3;
    const int lchk = tid & 7;
    const uint32_t dsw0 = (uint32_t)(lrow * 128 + ((lchk ^ (lrow & 7)) << 4));
    const __half* gA0 = xh + (size_t)(m0 + lrow) * K_TOTAL + lchk * 8;
    const __half* gB0 = wh + (size_t)(n0 + lrow) * K_TOTAL + lchk * 8;

    auto load_stage = [&](int stage, int k0) {
        uint32_t sbase = sb + stage * STAGE_BYTES + dsw0;
        const __half* pA = gA0 + k0;
        const __half* pB = gB0 + k0;
#pragma unroll
        for (int i = 0; i < 8; i++) {
            cp_async16(sbase + OFF_A + i * 2048, pA + (size_t)i * (16 * K_TOTAL));
            cp_async16(sbase + OFF_B + i * 2048, pB + (size_t)i * (16 * K_TOTAL));
        }
    };

    // ---- ldmatrix per-lane base terms ----
    const int a_row_l = warp_m * 64 + (lane & 15);
    const int a_kadd  = lane >> 4;
    const int b_row_l = warp_n * 64 + (lane & 7) + ((lane >> 4) << 3);
    const int b_kadd  = (lane >> 3) & 1;

    float acc[4][8][4];
#pragma unroll
    for (int mt = 0; mt < 4; mt++)
#pragma unroll
        for (int nt = 0; nt < 8; nt++)
#pragma unroll
            for (int j = 0; j < 4; j++) acc[mt][nt][j] = 0.0f;

    // ---- prologue ----
    load_stage(0, 0);
    CP_COMMIT();
    load_stage(1, KT);
    CP_COMMIT();

    uint32_t a[4][4], b[8][2];

    auto ld_frags = [&](int kc, uint32_t sA, uint32_t sB) {
#pragma unroll
        for (int mt = 0; mt < 4; mt++) {
            int row = a_row_l + mt * 16;
            int ch = kc * 2 + a_kadd;
            uint32_t off = (uint32_t)(row * 128 + ((ch ^ (row & 7)) << 4));
            ldsm_x4(a[mt], sA + off);
        }
#pragma unroll
        for (int np = 0; np < 4; np++) {
            int row = b_row_l + np * 16;
            int ch = kc * 2 + b_kadd;
            uint32_t off = (uint32_t)(row * 128 + ((ch ^ (row & 7)) << 4));
            uint32_t t[4];
            ldsm_x4(t, sB + off);
            b[np * 2][0] = t[0]; b[np * 2][1] = t[1];
            b[np * 2 + 1][0] = t[2]; b[np * 2 + 1][1] = t[3];
        }
    };

    // ---- mainloop ----
    for (int ks = 0; ks < KITERS; ks++) {
        CP_WAIT1();
        __syncthreads();

        const uint32_t sbase = sb + (ks % NSTAGE) * STAGE_BYTES;
        const uint32_t sA = sbase + OFF_A;
        const uint32_t sB = sbase + OFF_B;

        // issue kc0 fragment loads FIRST, so the cp.async burst below
        // executes inside the LDSM->MMA dependency shadow
        ld_frags(0, sA, sB);

        if (ks + 2 < KITERS) load_stage((ks + 2) % NSTAGE, (ks + 2) * KT);
        CP_COMMIT();

#pragma unroll
        for (int kc = 0; kc < 4; kc++) {
#pragma unroll
            for (int mt = 0; mt < 4; mt++) {
#pragma unroll
                for (int nt = 0; nt < 8; nt++) {
                    mma16816(acc[mt][nt], a[mt], b[nt]);
                }
            }
            if (kc < 3) ld_frags(kc + 1, sA, sB);
        }
    }

    // ---- epilogue: bias + store ----
    const int r0 = lane >> 2;
    const int c0 = (lane & 3) * 2;
#pragma unroll
    for (int mt = 0; mt < 4; mt++) {
        int row = m0 + warp_m * 64 + mt * 16 + r0;
#pragma unroll
        for (int nt = 0; nt < 8; nt++) {
            int col = n0 + warp_n * 64 + nt * 8 + c0;
            float bx = __ldg(bias + col);
            float by = __ldg(bias + col + 1);
            float2 v0 = make_float2(acc[mt][nt][0] + bx, acc[mt][nt][1] + by);
            float2 v1 = make_float2(acc[mt][nt][2] + bx, acc[mt][nt][3] + by);
            *(float2*)(out + (size_t)row * N_TOTAL + col) = v0;
            *(float2*)(out + (size_t)(row + 8) * N_TOTAL + col) = v1;
        }
    }
}

// ---------------------------------------------------------------------------
// Host side
// ---------------------------------------------------------------------------
extern "C" void kernel_launch(void* const* d_in, const int* in_sizes, int n_in,
                              void* d_out, int out_size) {
    const float* x    = (const float*)d_in[0];
    const float* w    = (const float*)d_in[1];
    const float* bias = (const float*)d_in[2];
    float* out = (float*)d_out;

    __half *xh, *wh;
    cudaGetSymbolAddress((void**)&xh, g_xh);
    cudaGetSymbolAddress((void**)&wh, g_wh);

    {
        int n16x = (M_TOTAL * K_TOTAL) / 16;   // 1,048,576
        int n16w = (N_TOTAL * K_TOTAL) / 16;   //   262,144
        int total = n16x + n16w;
        convert_both_kernel<<<(total + 255) / 256, 256>>>(
            (const float4*)x, (float4*)xh, n16x,
            (const float4*)w, (float4*)wh, n16w);
    }

    static bool attr_set = false;
    if (!attr_set) {
        cudaFuncSetAttribute(fp16_gemm_kernel,
                             cudaFuncAttributeMaxDynamicSharedMemorySize, SMEM_REQ);
        attr_set = true;
    }
    fp16_gemm_kernel<<<M_TILES * N_TILES, 128, SMEM_REQ>>>(out, bias, xh, wh);
}